// round 6
// baseline (speedup 1.0000x reference)
#include <cuda_runtime.h>

#define B_ 8
#define C_ 64
#define H_ 256
#define W_ 256
#define E_ 256
#define NH_ 8
#define HD_ 32
#define NPIX (H_*W_)

// half-row tile: 128 pixels
#define TP 128
#define NCH (H_*2)            // chunks per batch image = 512

// shared layout (floats): xs[128*64] | la[128*12] | w8[64*16] | red[104] | srow[8] | sbv[8]
#define XS_F   (TP*64)
#define LA_F   (TP*12)
#define W8_F   (64*16)
#define RED_F  104
#define SMEM_FLOATS (XS_F + LA_F + W8_F + RED_F + 16)

__device__ float g_wa[B_*NH_*C_];
__device__ float g_wb[B_*NH_*C_];
__device__ float g_wc[B_*NH_*C_];
__device__ float g_s [B_*NH_*3];
__device__ float g_part[(size_t)B_*NCH*NH_*68];   // per (b,chunk,h): S[64], m, T, PJ, pad

#define FMA2(a, x, w) asm("fma.rn.f32x2 %0, %1, %2, %0;" : "+l"(a) : "l"(x), "l"(w))

// ---------------------------------------------------------------------------
// Prep: per (b,h) build wa/wb/wc[64] and scalars sa/sb/sc. 256 threads.
// ---------------------------------------------------------------------------
__global__ void prep_kernel(const float* __restrict__ z,  const float* __restrict__ pos,
                            const float* __restrict__ Wq, const float* __restrict__ bq,
                            const float* __restrict__ Wk, const float* __restrict__ bk,
                            const float* __restrict__ Wp, const float* __restrict__ bp)
{
    int b = blockIdx.x >> 3, h = blockIdx.x & 7;
    __shared__ float tA[HD_], tB[HD_], tC[HD_];
    int tid = threadIdx.x;
    const float s = 0.1767766952966369f;  // 1/sqrt(32)

    {
        int d = tid >> 3, q = tid & 7;
        int e = h*HD_ + d;
        const float4* zr = reinterpret_cast<const float4*>(z + b*C_);
        const float4* wq = reinterpret_cast<const float4*>(Wq + e*C_);
        float4 z0 = zr[q*2], z1 = zr[q*2+1];
        float4 w0 = __ldg(wq + q*2), w1 = __ldg(wq + q*2 + 1);
        float qv = z0.x*w0.x + z0.y*w0.y + z0.z*w0.z + z0.w*w0.w
                 + z1.x*w1.x + z1.y*w1.y + z1.z*w1.z + z1.w*w1.w;
        qv += __shfl_xor_sync(0xffffffffu, qv, 1);
        qv += __shfl_xor_sync(0xffffffffu, qv, 2);
        qv += __shfl_xor_sync(0xffffffffu, qv, 4);
        if (q == 0) {
            qv += bq[e];
            float wp0 = Wp[2*d], wp1 = Wp[2*d+1];
            float p0 = pos[(b*NH_+h)*2], p1 = pos[(b*NH_+h)*2+1];
            float cc = bp[d] - wp0*p0 - wp1*p1;
            tA[d] = qv*wp0*s; tB[d] = qv*wp1*s; tC[d] = qv*cc*s;
        }
    }
    __syncthreads();
    {
        int c = tid >> 2, sub = tid & 3;
        const float* wkb = Wk + h*HD_*C_ + c;
        float a = 0.f, bb = 0.f, cc = 0.f;
        #pragma unroll
        for (int d = sub*8; d < sub*8+8; d++) {
            float w = __ldg(wkb + d*C_);
            a += tA[d]*w; bb += tB[d]*w; cc += tC[d]*w;
        }
        a  += __shfl_xor_sync(0xffffffffu, a, 1);
        bb += __shfl_xor_sync(0xffffffffu, bb, 1);
        cc += __shfl_xor_sync(0xffffffffu, cc, 1);
        a  += __shfl_xor_sync(0xffffffffu, a, 2);
        bb += __shfl_xor_sync(0xffffffffu, bb, 2);
        cc += __shfl_xor_sync(0xffffffffu, cc, 2);
        if (sub == 0) {
            int base = (b*NH_+h)*C_;
            g_wa[base+c] = a; g_wb[base+c] = bb; g_wc[base+c] = cc;
        }
    }
    if (tid < 3) {
        const float* t = (tid==0) ? tA : ((tid==1) ? tB : tC);
        float sv = 0.f;
        #pragma unroll
        for (int d = 0; d < HD_; d++) sv += t[d]*bk[h*HD_+d];
        g_s[(b*NH_+h)*3 + tid] = sv;
    }
}

// ---------------------------------------------------------------------------
// Main: one block per (b, half-row of 128 px). 128 threads, occ 5.
// xs swizzled: word(p,c) = p*64 + ((c + 8*(p&3) + (p>>2)) & 63)
// ---------------------------------------------------------------------------
__global__ void __launch_bounds__(128, 5) main_kernel(const float* __restrict__ x)
{
    extern __shared__ float sm[];
    float* xs   = sm;                      // [128*64] swizzled
    float* la   = sm + XS_F;               // [128][12]
    float* w8   = la + LA_F;               // [64][16]; reused as Sp in phase B
    float* red  = w8 + W8_F;
    float* srow = red + RED_F;
    float* sbv  = srow + 8;
    float* red_m = red, *red_t = red + 32, *red_pj = red + 64, *mfin = red + 96;

    int bx = blockIdx.x;
    int row = bx >> 1, half = bx & 1;
    int b = blockIdx.y;
    int tid = threadIdx.x;
    int warp = tid >> 5, lane = tid & 31;

    // stage 128-px half-row: 8 LDG.128 in flight per batch, swizzled scatter
    {
        const float* xg = x + (size_t)b*C_*NPIX + (size_t)row*W_ + half*TP;
        #pragma unroll
        for (int r = 0; r < 2; r++) {
            float4 v[8];
            #pragma unroll
            for (int j = 0; j < 8; j++) {
                int idx = tid + (r*8 + j)*128;   // 0..2047
                int c = idx >> 5, q = idx & 31;
                v[j] = __ldg(reinterpret_cast<const float4*>(xg + (size_t)c*NPIX) + q);
            }
            #pragma unroll
            for (int j = 0; j < 8; j++) {
                int idx = tid + (r*8 + j)*128;
                int c = idx >> 5, q = idx & 31;
                int base = q*4*64;
                xs[base       + ((c + q     ) & 63)] = v[j].x;
                xs[base + 64  + ((c + q +  8) & 63)] = v[j].y;
                xs[base + 128 + ((c + q + 16) & 63)] = v[j].z;
                xs[base + 192 + ((c + q + 24) & 63)] = v[j].w;
            }
        }
    }

    // per-row combined weights
    if (tid < 64) {
        int c = tid;
        float rf = (float)row;
        #pragma unroll
        for (int h = 0; h < 8; h++) {
            int gi = (b*NH_+h)*C_ + c;
            w8[c*16 + 2*h]     = g_wc[gi] + rf*g_wa[gi];
            w8[c*16 + 2*h + 1] = g_wb[gi];
        }
    } else if (tid < 72) {
        int h = tid - 64;
        srow[h] = g_s[(b*NH_+h)*3+2] + (float)row*g_s[(b*NH_+h)*3+0];
        sbv[h]  = g_s[(b*NH_+h)*3+1];
    }
    __syncthreads();

    // ---- Phase A: logits, 1 pixel per thread
    int p = tid;
    int colg = half*TP + tid;
    float l[8];
    {
        unsigned long long acc[8];
        #pragma unroll
        for (int h = 0; h < 8; h++) acc[h] = 0ULL;
        const float* xr = xs + p*64;
        int G = ((p & 3) << 3) + (p >> 2);
        #pragma unroll 4
        for (int c = 0; c < 64; c++) {
            float xv = xr[(c + G) & 63];
            unsigned long long xx;
            asm("mov.b64 %0, {%1, %1};" : "=l"(xx) : "f"(xv));
            const ulonglong2* wp = reinterpret_cast<const ulonglong2*>(w8 + c*16);
            ulonglong2 wA = wp[0], wB = wp[1];
            FMA2(acc[0], xx, wA.x);
            FMA2(acc[1], xx, wA.y);
            FMA2(acc[2], xx, wB.x);
            FMA2(acc[3], xx, wB.y);
            ulonglong2 wC = wp[2], wD = wp[3];
            FMA2(acc[4], xx, wC.x);
            FMA2(acc[5], xx, wC.y);
            FMA2(acc[6], xx, wD.x);
            FMA2(acc[7], xx, wD.y);
        }
        float cf = (float)colg;
        #pragma unroll
        for (int h = 0; h < 8; h++) {
            float r, bb;
            asm("mov.b64 {%0, %1}, %2;" : "=f"(r), "=f"(bb) : "l"(acc[h]));
            l[h] = (r + srow[h]) + cf*(bb + sbv[h]);
        }
    }

    // ---- softmax partials over the 128-px chunk
    {
        float mh[8];
        #pragma unroll
        for (int h = 0; h < 8; h++) mh[h] = l[h];
        #pragma unroll
        for (int o = 16; o; o >>= 1) {
            #pragma unroll
            for (int h = 0; h < 8; h++)
                mh[h] = fmaxf(mh[h], __shfl_xor_sync(0xffffffffu, mh[h], o));
        }
        if (lane == 0) {
            #pragma unroll
            for (int h = 0; h < 8; h++) red_m[warp*8 + h] = mh[h];
        }
        __syncthreads();
        if (tid < 8)
            mfin[tid] = fmaxf(fmaxf(red_m[tid], red_m[8+tid]),
                              fmaxf(red_m[16+tid], red_m[24+tid]));
        __syncthreads();

        float th[8], pjh[8], e[8];
        float cf = (float)colg;
        #pragma unroll
        for (int h = 0; h < 8; h++) {
            e[h] = __expf(l[h] - mfin[h]);
            th[h]  = e[h];
            pjh[h] = e[h]*cf;
        }
        *reinterpret_cast<float4*>(la + p*12)     = make_float4(e[0], e[1], e[2], e[3]);
        *reinterpret_cast<float4*>(la + p*12 + 4) = make_float4(e[4], e[5], e[6], e[7]);

        #pragma unroll
        for (int o = 16; o; o >>= 1) {
            #pragma unroll
            for (int h = 0; h < 8; h++) {
                th[h]  += __shfl_xor_sync(0xffffffffu, th[h],  o);
                pjh[h] += __shfl_xor_sync(0xffffffffu, pjh[h], o);
            }
        }
        if (lane == 0) {
            #pragma unroll
            for (int h = 0; h < 8; h++) {
                red_t[warp*8 + h]  = th[h];
                red_pj[warp*8 + h] = pjh[h];
            }
        }
        __syncthreads();
        if (tid < 8) {
            float T  = red_t[tid]  + red_t[8+tid]  + red_t[16+tid]  + red_t[24+tid];
            float PJ = red_pj[tid] + red_pj[8+tid] + red_pj[16+tid] + red_pj[24+tid];
            size_t pb = ((size_t)(b*NCH + bx)*NH_ + tid)*68;
            g_part[pb + 64] = mfin[tid];
            g_part[pb + 65] = T;
            g_part[pb + 66] = PJ;
        }
    }

    // ---- Phase B: S[h][c] = sum_p e[p][h]*x[p][c], head-pairs via FMA2
    {
        int c = tid & 63, g = tid >> 6;
        unsigned long long acc[4];
        #pragma unroll
        for (int j = 0; j < 4; j++) acc[j] = 0ULL;
        int pbase = g*64;
        #pragma unroll 4
        for (int i = 0; i < 64; i++) {
            int pp = pbase + i;
            int col = (c + ((pp & 3) << 3) + (pp >> 2)) & 63;
            float xv = xs[pp*64 + col];
            unsigned long long xx;
            asm("mov.b64 %0, {%1, %1};" : "=l"(xx) : "f"(xv));
            ulonglong2 eA = *reinterpret_cast<const ulonglong2*>(la + pp*12);
            ulonglong2 eB = *reinterpret_cast<const ulonglong2*>(la + pp*12 + 4);
            FMA2(acc[0], xx, eA.x);
            FMA2(acc[1], xx, eA.y);
            FMA2(acc[2], xx, eB.x);
            FMA2(acc[3], xx, eB.y);
        }
        float* Sp = w8;  // reuse
        __syncthreads();
        *reinterpret_cast<ulonglong2*>(Sp + tid*8)     = make_ulonglong2(acc[0], acc[1]);
        *reinterpret_cast<ulonglong2*>(Sp + tid*8 + 4) = make_ulonglong2(acc[2], acc[3]);
        __syncthreads();
        if (tid < 64) {
            size_t chk = (size_t)(b*NCH + bx)*NH_;
            #pragma unroll
            for (int h = 0; h < 8; h++)
                g_part[(chk + h)*68 + tid] = Sp[tid*8 + h] + Sp[(tid+64)*8 + h];
        }
    }
}

// ---------------------------------------------------------------------------
// Combine: per (b,h) rescale 512 chunk-partials, project values, emit outputs.
// ---------------------------------------------------------------------------
__global__ void combine_kernel(const float* __restrict__ Wv, const float* __restrict__ bv,
                               float* __restrict__ out)
{
    int b = blockIdx.x >> 3, h = blockIdx.x & 7;
    __shared__ float fsh[NCH], Ssh[64], Sp[4][64];
    __shared__ float wred[8], wsum[8][3];
    __shared__ float Msh;
    int tid = threadIdx.x, warp = tid >> 5, lane = tid & 31;

    const float* pb0 = g_part + ((size_t)(b*NCH + tid)*NH_ + h)*68;
    const float* pb1 = g_part + ((size_t)(b*NCH + tid + 256)*NH_ + h)*68;
    float m0 = pb0[64], T0 = pb0[65], PJ0 = pb0[66];
    float m1 = pb1[64], T1 = pb1[65], PJ1 = pb1[66];

    float mm = fmaxf(m0, m1);
    #pragma unroll
    for (int o = 16; o; o >>= 1) mm = fmaxf(mm, __shfl_xor_sync(0xffffffffu, mm, o));
    if (lane == 0) wred[warp] = mm;
    __syncthreads();
    if (tid == 0) {
        float M = wred[0];
        #pragma unroll
        for (int i = 1; i < 8; i++) M = fmaxf(M, wred[i]);
        Msh = M;
    }
    __syncthreads();
    float M = Msh;
    float f0 = __expf(m0 - M), f1 = __expf(m1 - M);
    fsh[tid] = f0; fsh[tid + 256] = f1;
    float t0 = T0*f0, t1 = T1*f1;
    float Tl = t0 + t1;
    float P0 = t0*(float)(tid >> 1) + t1*(float)((tid + 256) >> 1);
    float P1 = PJ0*f0 + PJ1*f1;
    #pragma unroll
    for (int o = 16; o; o >>= 1) {
        Tl += __shfl_xor_sync(0xffffffffu, Tl, o);
        P0 += __shfl_xor_sync(0xffffffffu, P0, o);
        P1 += __shfl_xor_sync(0xffffffffu, P1, o);
    }
    if (lane == 0) { wsum[warp][0] = Tl; wsum[warp][1] = P0; wsum[warp][2] = P1; }
    __syncthreads();
    float Tsh = 0.f, P0sh = 0.f, P1sh = 0.f;
    #pragma unroll
    for (int i = 0; i < 8; i++) { Tsh += wsum[i][0]; P0sh += wsum[i][1]; P1sh += wsum[i][2]; }

    int c = tid & 63, seg = tid >> 6;
    float sacc = 0.f;
    const float* pbase = g_part + ((size_t)(b*NCH + seg*128)*NH_ + h)*68 + c;
    #pragma unroll 4
    for (int i = 0; i < 128; i++)
        sacc += pbase[(size_t)i*NH_*68] * fsh[seg*128 + i];
    Sp[seg][c] = sacc; __syncthreads();
    if (tid < 64) Ssh[tid] = (Sp[0][tid] + Sp[1][tid] + Sp[2][tid] + Sp[3][tid]) / Tsh;
    __syncthreads();

    int e = tid;
    float acc = bv[e];
    const float4* wv = reinterpret_cast<const float4*>(Wv + e*C_);
    const float4* ss = reinterpret_cast<const float4*>(Ssh);
    #pragma unroll
    for (int c2 = 0; c2 < 16; c2++) {
        float4 w = __ldg(wv + c2), sv = ss[c2];
        acc += w.x*sv.x + w.y*sv.y + w.z*sv.z + w.w*sv.w;
    }
    out[(size_t)(b*NH_+h)*E_ + e] = acc;

    if (tid == 0) {
        float invT = 1.f/Tsh;
        out[B_*NH_*E_ + (b*NH_+h)*2]     = P0sh*invT;
        out[B_*NH_*E_ + (b*NH_+h)*2 + 1] = P1sh*invT;
    }
}

extern "C" void kernel_launch(void* const* d_in, const int* in_sizes, int n_in,
                              void* d_out, int out_size)
{
    const float* x   = (const float*)d_in[0];
    const float* z   = (const float*)d_in[1];
    const float* pos = (const float*)d_in[2];
    const float* Wq  = (const float*)d_in[3];
    const float* bq  = (const float*)d_in[4];
    const float* Wk  = (const float*)d_in[5];
    const float* bk  = (const float*)d_in[6];
    const float* Wv  = (const float*)d_in[7];
    const float* bv  = (const float*)d_in[8];
    const float* Wp  = (const float*)d_in[9];
    const float* bp  = (const float*)d_in[10];
    float* out = (float*)d_out;

    cudaFuncSetAttribute(main_kernel, cudaFuncAttributeMaxDynamicSharedMemorySize,
                         SMEM_FLOATS * (int)sizeof(float));

    prep_kernel<<<B_*NH_, 256>>>(z, pos, Wq, bq, Wk, bk, Wp, bp);
    main_kernel<<<dim3(NCH, B_), 128, SMEM_FLOATS * sizeof(float)>>>(x);
    combine_kernel<<<B_*NH_, 256>>>(Wv, bv, out);
}